// round 17
// baseline (speedup 1.0000x reference)
#include <cuda_runtime.h>
#include <cuda_bf16.h>

#define MAX_ROWS 8192
#define MAX_PART 65536
#define SEG_F4   1000          // float4 per segment = 16 KB

__device__ float        g_part[MAX_PART];
__device__ float        g_target[MAX_ROWS];
__device__ double       g_row_loss[MAX_ROWS];
__device__ unsigned int g_rowcnt[MAX_ROWS];   // zero-init; self-resetting
__device__ unsigned int g_done = 0;           // self-resetting

__device__ __forceinline__ float ex2(float x) {
    float y;
    asm("ex2.approx.f32 %0, %1;" : "=f"(y) : "f"(x));
    return y;
}
__device__ __forceinline__ float lg2(float x) {
    float y;
    asm("lg2.approx.f32 %0, %1;" : "=f"(y) : "f"(x));
    return y;
}

// Fused segment sweep (R14-16: dense 16KB contiguous segments -> ~6.9 TB/s;
// row-per-block footprint was the ~5 TB/s cap) + in-kernel epilogue:
//  - covering block stashes the row's target value (line is cache-hot),
//  - 8th segment block per row runs the fp32 row epilogue (distributed,
//    overlapped with the sweep),
//  - last row-finisher does the deterministic fixed-order mean.
// Removes the second launch that cost 7.7us at 0.6% DRAM in R16.
__global__ void __launch_bounds__(256) cosarc_fused_kernel(
    const float* __restrict__ preds,
    const int* __restrict__ labels,     // int32 (JAX x64 disabled)
    float* __restrict__ out,
    int V, int B, int n4, int nspr)
{
    const int b   = blockIdx.x;
    const int row = b / nspr;
    const int seg = b - row * nspr;
    const int base = seg * SEG_F4;

    const float4* p4 = reinterpret_cast<const float4*>(preds) + (size_t)row * n4 + base;
    const int lim = min(SEG_F4, n4 - base);

    const int tid = threadIdx.x;
    const float C = 30.0f * 1.4426950408889634f;   // exp(30x) = exp2(C*x)
    float s0 = 0.f, s1 = 0.f, s2 = 0.f, s3 = 0.f;

    // 4 front-batched independent LDG.128 (covers 1024 >= SEG_F4).
    const int i0 = tid, i1 = tid + 256, i2 = tid + 512, i3 = tid + 768;
    float4 a, bb, c, d;
    bool v0 = i0 < lim, v1 = i1 < lim, v2 = i2 < lim, v3 = i3 < lim;
    if (v0) a  = __ldg(p4 + i0);
    if (v1) bb = __ldg(p4 + i1);
    if (v2) c  = __ldg(p4 + i2);
    if (v3) d  = __ldg(p4 + i3);
    if (v0) { s0 += ex2(a.x  * C) + ex2(a.y  * C); s1 += ex2(a.z  * C) + ex2(a.w  * C); }
    if (v1) { s2 += ex2(bb.x * C) + ex2(bb.y * C); s3 += ex2(bb.z * C) + ex2(bb.w * C); }
    if (v2) { s0 += ex2(c.x  * C) + ex2(c.y  * C); s1 += ex2(c.z  * C) + ex2(c.w  * C); }
    if (v3) { s2 += ex2(d.x  * C) + ex2(d.y  * C); s3 += ex2(d.z  * C) + ex2(d.w  * C); }

    float sum = (s0 + s1) + (s2 + s3);
    #pragma unroll
    for (int o = 16; o > 0; o >>= 1)
        sum += __shfl_xor_sync(0xffffffffu, sum, o);

    __shared__ float warpsum[8];
    const int wid = tid >> 5, lid = tid & 31;
    if (lid == 0) warpsum[wid] = sum;
    __syncthreads();

    __shared__ bool row_last, glob_last;
    if (tid == 0) {
        float tot = 0.f;
        #pragma unroll
        for (int w = 0; w < 8; w++) tot += warpsum[w];
        g_part[b] = tot;

        int lab = labels[row];
        if (lab < 0) lab = 0;
        if (lab >= V) lab = V - 1;
        const int lab4 = lab >> 2;
        if (lab4 >= base && lab4 < base + lim)          // this block streamed it
            g_target[row] = __ldg(preds + (size_t)row * V + lab);

        __threadfence();
        unsigned cnt = atomicAdd(&g_rowcnt[row], 1u);
        row_last = (cnt == (unsigned)(nspr - 1));
        glob_last = false;
    }
    __syncthreads();

    if (row_last) {
        if (tid == 0) {
            g_rowcnt[row] = 0;                          // reset for graph replay

            float tot = 0.f;
            #pragma unroll 8
            for (int s = 0; s < nspr; s++)
                tot += g_part[row * nspr + s];
            const float target = g_target[row];

            float sum_others = tot - ex2(target * C);

            const float PI = 3.14159265358979323846f;
            const float LOG2E = 1.4426950408889634f;
            const float LN2   = 0.6931471805599453f;
            float t = fminf(fmaxf(target, -1.0f + 1e-12f), 1.0f - 1e-7f);
            float theta = acosf(t);
            theta = fminf(fmaxf(theta, 1e-12f), PI - 1e-7f);
            float numerator = 30.0f * (__cosf(theta + 0.5f) - 0.35f);
            float denominator = ex2(numerator * LOG2E) + sum_others;
            g_row_loss[row] = (double)(numerator - lg2(denominator) * LN2);

            __threadfence();
            unsigned dc = atomicAdd(&g_done, 1u);
            glob_last = (dc == (unsigned)(B - 1));
        }
        __syncthreads();

        if (glob_last) {
            // Deterministic fixed-order mean over row losses.
            double acc = 0.0;
            for (int j = tid; j < B; j += 256)
                acc += g_row_loss[j];

            #pragma unroll
            for (int o = 16; o > 0; o >>= 1)
                acc += __shfl_xor_sync(0xffffffffu, acc, o);

            __shared__ double dwarp[8];
            if (lid == 0) dwarp[wid] = acc;
            __syncthreads();

            if (tid == 0) {
                double tot = 0.0;
                #pragma unroll
                for (int w = 0; w < 8; w++) tot += dwarp[w];
                out[0] = (float)(-tot / (double)B);
                g_done = 0;                             // reset for graph replay
            }
        }
    }
}

extern "C" void kernel_launch(void* const* d_in, const int* in_sizes, int n_in,
                              void* d_out, int out_size)
{
    const float* preds  = (const float*)d_in[0];
    const int*   labels = (const int*)d_in[1];

    const int B  = in_sizes[1];                 // 2048
    const int V  = in_sizes[0] / B;             // 32000
    const int n4 = V >> 2;                      // 8000 (V % 4 == 0 here)
    const int nspr = (n4 + SEG_F4 - 1) / SEG_F4;   // 8

    cosarc_fused_kernel<<<B * nspr, 256>>>(preds, labels, (float*)d_out, V, B, n4, nspr);
}